// round 6
// baseline (speedup 1.0000x reference)
#include <cuda_runtime.h>
#include <stdint.h>

#define EPSF 1e-6f

#define NB 32
#define NS 8
#define HW 65536
#define HW4 (HW / 4)
#define NACC 66
// per-batch accumulator layout:
//   [0..48]  fg inter[p*7+g]  (pred slot p+1, gt slot g+1)
//   [49..56] sum_pred[s], [57..64] sum_gt[s], [65] bg inter

#define NCHUNK 16
#define TPB 128

__device__ float g_part[NB][NCHUNK][NACC];
__device__ float g_bg[NB];
__device__ float g_fg[NB];
__device__ int   g_n[NB];
__device__ int   cnt_batch[NB];   // zero-initialized; reset by kernel each run
__device__ int   cnt_global;

__device__ __forceinline__ float warp_sum(float v) {
    #pragma unroll
    for (int off = 16; off > 0; off >>= 1)
        v += __shfl_down_sync(0xffffffffu, v, off);
    return v;
}

__global__ __launch_bounds__(TPB, 3)
void fused_kernel(const float* __restrict__ pred, const float* __restrict__ gt,
                  const int* __restrict__ num_objects, float* __restrict__ out) {
    const int b = blockIdx.x / NCHUNK;
    const int chunk = blockIdx.x % NCHUNK;
    const int cbase = chunk * (HW4 / NCHUNK);   // in float4 units

    const float4* __restrict__ pb = (const float4*)(pred + (size_t)b * NS * HW);
    const float4* __restrict__ gb = (const float4*)(gt   + (size_t)b * NS * HW);

    float inter[49];
    float sp[8], sg[8];
    float bgi = 0.0f;
    #pragma unroll
    for (int k = 0; k < 49; k++) inter[k] = 0.0f;
    #pragma unroll
    for (int s = 0; s < 8; s++) { sp[s] = 0.0f; sg[s] = 0.0f; }

    const int cend = cbase + HW4 / NCHUNK;
    for (int pix = cbase + threadIdx.x; pix < cend; pix += TPB) {
        float4 p[8];
        #pragma unroll
        for (int s = 0; s < 8; s++) p[s] = pb[s * HW4 + pix];
        #pragma unroll
        for (int s = 0; s < 8; s++)
            sp[s] += (p[s].x + p[s].y) + (p[s].z + p[s].w);

        {   // gt slot 0: background
            float4 g0 = gb[pix];
            sg[0] += (g0.x + g0.y) + (g0.z + g0.w);
            bgi = fmaf(p[0].x, g0.x, bgi);
            bgi = fmaf(p[0].y, g0.y, bgi);
            bgi = fmaf(p[0].z, g0.z, bgi);
            bgi = fmaf(p[0].w, g0.w, bgi);
        }
        #pragma unroll
        for (int j = 1; j < 8; j++) {
            float4 g = gb[j * HW4 + pix];
            sg[j] += (g.x + g.y) + (g.z + g.w);
            #pragma unroll
            for (int i = 1; i < 8; i++) {
                float acc = inter[(i - 1) * 7 + (j - 1)];
                acc = fmaf(p[i].x, g.x, acc);
                acc = fmaf(p[i].y, g.y, acc);
                acc = fmaf(p[i].z, g.z, acc);
                acc = fmaf(p[i].w, g.w, acc);
                inter[(i - 1) * 7 + (j - 1)] = acc;
            }
        }
    }

    // ---- block reduction -> g_part[b][chunk][*] ----
    __shared__ float wsum[TPB / 32][NACC];
    __shared__ float a_sm[NACC];
    __shared__ float dice_sm[49];
    __shared__ float dp_sm[128];
    __shared__ int   flag_sm;

    const int wid = threadIdx.x >> 5;
    const int lane = threadIdx.x & 31;

    #pragma unroll
    for (int k = 0; k < 49; k++) {
        float v = warp_sum(inter[k]);
        if (lane == 0) wsum[wid][k] = v;
    }
    #pragma unroll
    for (int s = 0; s < 8; s++) {
        float v = warp_sum(sp[s]);
        if (lane == 0) wsum[wid][49 + s] = v;
    }
    #pragma unroll
    for (int s = 0; s < 8; s++) {
        float v = warp_sum(sg[s]);
        if (lane == 0) wsum[wid][57 + s] = v;
    }
    {
        float v = warp_sum(bgi);
        if (lane == 0) wsum[wid][65] = v;
    }
    __syncthreads();
    if (threadIdx.x < NACC) {
        float v = 0.0f;
        #pragma unroll
        for (int w = 0; w < TPB / 32; w++) v += wsum[w][threadIdx.x];
        g_part[b][chunk][threadIdx.x] = v;
    }
    __threadfence();
    __syncthreads();

    // ---- last block of this batch runs the batch finalize ----
    if (threadIdx.x == 0) {
        int old = atomicAdd(&cnt_batch[b], 1);
        flag_sm = (old == NCHUNK - 1) ? 1 : 0;
    }
    __syncthreads();
    if (!flag_sm) return;
    __threadfence();   // acquire: see all chunks' g_part writes

    if (wid == 0) {
        // sum partials over chunks
        for (int k = lane; k < NACC; k += 32) {
            float v = 0.0f;
            #pragma unroll
            for (int c = 0; c < NCHUNK; c++) v += g_part[b][c][k];
            a_sm[k] = v;
        }
        __syncwarp();

        // dice matrix (pred p, gt g) — all 49 entries
        for (int idx = lane; idx < 49; idx += 32) {
            int p = idx / 7, g = idx % 7;
            dice_sm[idx] = (2.0f * a_sm[idx] + EPSF) /
                           (a_sm[50 + p] + a_sm[58 + g] + EPSF);
        }
        __syncwarp();

        int n = num_objects[b];
        if (n > 7) n = 7;
        if (n < 0) n = 0;

        // subset DP over pred-slot sets (exact optimal-assignment sum)
        #pragma unroll
        for (int q = 0; q < 4; q++) {
            int S = lane + 32 * q;
            dp_sm[S] = (S == 0) ? 0.0f : -1e30f;
        }
        __syncwarp();
        for (int k = 1; k <= n; k++) {
            float newv[4];
            #pragma unroll
            for (int q = 0; q < 4; q++) {
                int S = lane + 32 * q;
                float best = -1e30f;
                if (__popc(S) == k) {
                    #pragma unroll
                    for (int j = 0; j < 7; j++) {
                        if (S & (1 << j)) {
                            float cand = dp_sm[S & ~(1 << j)] + dice_sm[j * 7 + (k - 1)];
                            best = fmaxf(best, cand);
                        }
                    }
                }
                newv[q] = best;
            }
            __syncwarp();
            #pragma unroll
            for (int q = 0; q < 4; q++) {
                int S = lane + 32 * q;
                if (__popc(S) == k) dp_sm[S] = newv[q];
            }
            __syncwarp();
        }

        float best = -1e30f;
        #pragma unroll
        for (int q = 0; q < 4; q++) {
            int S = lane + 32 * q;
            if (__popc(S) == n) best = fmaxf(best, dp_sm[S]);
        }
        #pragma unroll
        for (int off = 16; off > 0; off >>= 1)
            best = fmaxf(best, __shfl_down_sync(0xffffffffu, best, off));

        if (lane == 0) {
            g_bg[b] = 1.0f - (2.0f * a_sm[65] + EPSF) /
                             (a_sm[49] + a_sm[57] + EPSF);
            g_fg[b] = (n > 0) ? ((float)n - best) : 0.0f;
            g_n[b]  = n;
            __threadfence();

            // ---- global finalize by the last batch finalizer ----
            int gold = atomicAdd(&cnt_global, 1);
            if (gold == NB - 1) {
                __threadfence();
                float bg = 0.0f, fg = 0.0f;
                int cn = 0;
                #pragma unroll
                for (int bb = 0; bb < NB; bb++) {
                    bg += g_bg[bb];
                    fg += g_fg[bb];
                    cn += g_n[bb];
                }
                float bg_loss = bg / (float)NB;
                float fg_loss = (cn > 0) ? (fg / (float)cn) : 0.0f;
                out[0] = bg_loss + fg_loss;
                // reset counters for the next graph replay
                #pragma unroll
                for (int bb = 0; bb < NB; bb++) cnt_batch[bb] = 0;
                cnt_global = 0;
                __threadfence();
            }
        }
    }
}

extern "C" void kernel_launch(void* const* d_in, const int* in_sizes, int n_in,
                              void* d_out, int out_size) {
    const float* pred = (const float*)d_in[0];
    const float* gt   = (const float*)d_in[1];
    const int*   nobj = (const int*)d_in[2];
    float* out = (float*)d_out;

    fused_kernel<<<NB * NCHUNK, TPB>>>(pred, gt, nobj, out);
}

// round 10
// speedup vs baseline: 1.1529x; 1.1529x over previous
#include <cuda_runtime.h>
#include <stdint.h>

#define EPSF 1e-6f

#define NB 32
#define NS 8
#define HW 65536
#define HW2 (HW / 2)
#define NACC 66
// per-batch accumulator layout:
//   [0..48]  fg inter[p*7+g]  (pred slot p+1, gt slot g+1)
//   [49..56] sum_pred[s], [57..64] sum_gt[s], [65] bg inter

#define NCHUNK 18
#define TPB 128

__device__ float g_part[NB][NCHUNK][NACC];
__device__ float g_bg[NB];
__device__ float g_fg[NB];
__device__ int   g_n[NB];
__device__ int   cnt_batch[NB];   // zero-init; restored by kernel each run
__device__ int   cnt_global;

__device__ __forceinline__ float warp_sum(float v) {
    #pragma unroll
    for (int off = 16; off > 0; off >>= 1)
        v += __shfl_down_sync(0xffffffffu, v, off);
    return v;
}

__global__ __launch_bounds__(TPB, 4)
void fused_kernel(const float* __restrict__ pred, const float* __restrict__ gt,
                  const int* __restrict__ num_objects, float* __restrict__ out) {
    const int b = blockIdx.x / NCHUNK;
    const int chunk = blockIdx.x % NCHUNK;
    // range-based chunking in float2 units (no divisibility requirement)
    const int lo = (int)(((long long)chunk * HW2) / NCHUNK);
    const int hi = (int)(((long long)(chunk + 1) * HW2) / NCHUNK);

    const float2* __restrict__ pb = (const float2*)(pred + (size_t)b * NS * HW);
    const float2* __restrict__ gb = (const float2*)(gt   + (size_t)b * NS * HW);

    float inter[49];
    float sp[8], sg[8];
    float bgi = 0.0f;
    #pragma unroll
    for (int k = 0; k < 49; k++) inter[k] = 0.0f;
    #pragma unroll
    for (int s = 0; s < 8; s++) { sp[s] = 0.0f; sg[s] = 0.0f; }

    for (int pix = lo + threadIdx.x; pix < hi; pix += TPB) {
        float2 p[8];
        #pragma unroll
        for (int s = 0; s < 8; s++) p[s] = pb[s * HW2 + pix];
        #pragma unroll
        for (int s = 0; s < 8; s++) sp[s] += p[s].x + p[s].y;

        {   // gt slot 0 (background)
            float2 g0 = gb[pix];
            sg[0] += g0.x + g0.y;
            bgi = fmaf(p[0].x, g0.x, bgi);
            bgi = fmaf(p[0].y, g0.y, bgi);
        }
        #pragma unroll
        for (int j = 1; j < 8; j++) {
            float2 g = gb[j * HW2 + pix];
            sg[j] += g.x + g.y;
            #pragma unroll
            for (int i = 1; i < 8; i++) {
                float acc = inter[(i - 1) * 7 + (j - 1)];
                acc = fmaf(p[i].x, g.x, acc);
                acc = fmaf(p[i].y, g.y, acc);
                inter[(i - 1) * 7 + (j - 1)] = acc;
            }
        }
    }

    // ---- block reduction -> g_part[b][chunk][*] ----
    __shared__ float wsum[TPB / 32][NACC];
    __shared__ float a_sm[NACC];
    __shared__ float dice_sm[49];
    __shared__ float dp_sm[128];
    __shared__ int   flag_sm;

    const int wid = threadIdx.x >> 5;
    const int lane = threadIdx.x & 31;

    #pragma unroll
    for (int k = 0; k < 49; k++) {
        float v = warp_sum(inter[k]);
        if (lane == 0) wsum[wid][k] = v;
    }
    #pragma unroll
    for (int s = 0; s < 8; s++) {
        float v = warp_sum(sp[s]);
        if (lane == 0) wsum[wid][49 + s] = v;
    }
    #pragma unroll
    for (int s = 0; s < 8; s++) {
        float v = warp_sum(sg[s]);
        if (lane == 0) wsum[wid][57 + s] = v;
    }
    {
        float v = warp_sum(bgi);
        if (lane == 0) wsum[wid][65] = v;
    }
    __syncthreads();
    if (threadIdx.x < NACC) {
        float v = 0.0f;
        #pragma unroll
        for (int w = 0; w < TPB / 32; w++) v += wsum[w][threadIdx.x];
        g_part[b][chunk][threadIdx.x] = v;
    }
    __threadfence();
    __syncthreads();

    // ---- last block of this batch runs the batch finalize ----
    if (threadIdx.x == 0) {
        int old = atomicAdd(&cnt_batch[b], 1);
        flag_sm = (old == NCHUNK - 1) ? 1 : 0;
    }
    __syncthreads();
    if (!flag_sm) return;
    __threadfence();   // acquire: see all chunks' g_part writes

    if (wid == 0) {
        int n = num_objects[b];
        if (n > 7) n = 7;
        if (n < 0) n = 0;

        // sum partials over chunks
        for (int k = lane; k < NACC; k += 32) {
            float v = 0.0f;
            #pragma unroll
            for (int c = 0; c < NCHUNK; c++) v += g_part[b][c][k];
            a_sm[k] = v;
        }
        __syncwarp();

        // dice matrix (pred p, gt g) — all 49 entries
        for (int idx = lane; idx < 49; idx += 32) {
            int p = idx / 7, g = idx % 7;
            dice_sm[idx] = (2.0f * a_sm[idx] + EPSF) /
                           (a_sm[50 + p] + a_sm[58 + g] + EPSF);
        }
        __syncwarp();

        // subset DP over pred-slot sets (exact optimal-assignment sum)
        #pragma unroll
        for (int q = 0; q < 4; q++) {
            int S = lane + 32 * q;
            dp_sm[S] = (S == 0) ? 0.0f : -1e30f;
        }
        __syncwarp();
        for (int k = 1; k <= n; k++) {
            float newv[4];
            #pragma unroll
            for (int q = 0; q < 4; q++) {
                int S = lane + 32 * q;
                float best = -1e30f;
                if (__popc(S) == k) {
                    #pragma unroll
                    for (int j = 0; j < 7; j++) {
                        if (S & (1 << j)) {
                            float cand = dp_sm[S & ~(1 << j)] + dice_sm[j * 7 + (k - 1)];
                            best = fmaxf(best, cand);
                        }
                    }
                }
                newv[q] = best;
            }
            __syncwarp();
            #pragma unroll
            for (int q = 0; q < 4; q++) {
                int S = lane + 32 * q;
                if (__popc(S) == k) dp_sm[S] = newv[q];
            }
            __syncwarp();
        }

        float best = -1e30f;
        #pragma unroll
        for (int q = 0; q < 4; q++) {
            int S = lane + 32 * q;
            if (__popc(S) == n) best = fmaxf(best, dp_sm[S]);
        }
        #pragma unroll
        for (int off = 16; off > 0; off >>= 1)
            best = fmaxf(best, __shfl_down_sync(0xffffffffu, best, off));

        if (lane == 0) {
            g_bg[b] = 1.0f - (2.0f * a_sm[65] + EPSF) /
                             (a_sm[49] + a_sm[57] + EPSF);
            g_fg[b] = (n > 0) ? ((float)n - best) : 0.0f;
            g_n[b]  = n;
            __threadfence();

            // ---- global finalize by the last batch finalizer ----
            int gold = atomicAdd(&cnt_global, 1);
            if (gold == NB - 1) {
                __threadfence();
                float bg = 0.0f, fg = 0.0f;
                int cn = 0;
                #pragma unroll
                for (int bb = 0; bb < NB; bb++) {
                    bg += g_bg[bb];
                    fg += g_fg[bb];
                    cn += g_n[bb];
                }
                float bg_loss = bg / (float)NB;
                float fg_loss = (cn > 0) ? (fg / (float)cn) : 0.0f;
                out[0] = bg_loss + fg_loss;
                // reset counters for the next graph replay
                #pragma unroll
                for (int bb = 0; bb < NB; bb++) cnt_batch[bb] = 0;
                cnt_global = 0;
                __threadfence();
            }
        }
    }
}

extern "C" void kernel_launch(void* const* d_in, const int* in_sizes, int n_in,
                              void* d_out, int out_size) {
    const float* pred = (const float*)d_in[0];
    const float* gt   = (const float*)d_in[1];
    const int*   nobj = (const int*)d_in[2];
    float* out = (float*)d_out;

    fused_kernel<<<NB * NCHUNK, TPB>>>(pred, gt, nobj, out);
}

// round 11
// speedup vs baseline: 1.1612x; 1.0072x over previous
#include <cuda_runtime.h>
#include <stdint.h>

#define EPSF 1e-6f

#define NB 32
#define NS 8
#define HW 65536
#define HW2 (HW / 2)
#define NACC 66
// per-batch accumulator layout:
//   [0..48]  fg inter[p*7+g]  (pred slot p+1, gt slot g+1)
//   [49..56] sum_pred[s], [57..64] sum_gt[s], [65] bg inter

#define NCHUNK 13
#define TPB 128

__device__ float g_part[NB][NCHUNK][NACC];
__device__ float g_bg[NB];
__device__ float g_fg[NB];
__device__ int   g_n[NB];
__device__ int   cnt_batch[NB];   // zero-init; restored by kernel each run
__device__ int   cnt_global;

__device__ __forceinline__ float warp_sum(float v) {
    #pragma unroll
    for (int off = 16; off > 0; off >>= 1)
        v += __shfl_down_sync(0xffffffffu, v, off);
    return v;
}

__device__ __forceinline__ float2 ldcs2(const float2* p) {
    return __ldcs(p);
}

__global__ __launch_bounds__(TPB, 3)
void fused_kernel(const float* __restrict__ pred, const float* __restrict__ gt,
                  const int* __restrict__ num_objects, float* __restrict__ out) {
    const int b = blockIdx.x / NCHUNK;
    const int chunk = blockIdx.x % NCHUNK;
    // range-based chunking in float2 units (no divisibility requirement)
    const int lo = (int)(((long long)chunk * HW2) / NCHUNK);
    const int hi = (int)(((long long)(chunk + 1) * HW2) / NCHUNK);

    const float2* __restrict__ pb = (const float2*)(pred + (size_t)b * NS * HW);
    const float2* __restrict__ gb = (const float2*)(gt   + (size_t)b * NS * HW);

    float inter[49];
    float sp[8], sg[8];
    float bgi = 0.0f;
    #pragma unroll
    for (int k = 0; k < 49; k++) inter[k] = 0.0f;
    #pragma unroll
    for (int s = 0; s < 8; s++) { sp[s] = 0.0f; sg[s] = 0.0f; }

    for (int pix = lo + threadIdx.x; pix < hi; pix += TPB) {
        // batch ALL 16 loads first -> max MLP, then consume
        float2 p[8], g[8];
        #pragma unroll
        for (int s = 0; s < 8; s++) p[s] = ldcs2(&pb[s * HW2 + pix]);
        #pragma unroll
        for (int s = 0; s < 8; s++) g[s] = ldcs2(&gb[s * HW2 + pix]);

        #pragma unroll
        for (int s = 0; s < 8; s++) sp[s] += p[s].x + p[s].y;
        #pragma unroll
        for (int s = 0; s < 8; s++) sg[s] += g[s].x + g[s].y;

        bgi = fmaf(p[0].x, g[0].x, bgi);
        bgi = fmaf(p[0].y, g[0].y, bgi);
        #pragma unroll
        for (int i = 1; i < 8; i++)
            #pragma unroll
            for (int j = 1; j < 8; j++) {
                float acc = inter[(i - 1) * 7 + (j - 1)];
                acc = fmaf(p[i].x, g[j].x, acc);
                acc = fmaf(p[i].y, g[j].y, acc);
                inter[(i - 1) * 7 + (j - 1)] = acc;
            }
    }

    // ---- block reduction -> g_part[b][chunk][*] ----
    __shared__ float wsum[TPB / 32][NACC];
    __shared__ float a_sm[NACC];
    __shared__ float dice_sm[49];
    __shared__ float dp_sm[128];
    __shared__ int   flag_sm;

    const int wid = threadIdx.x >> 5;
    const int lane = threadIdx.x & 31;

    #pragma unroll
    for (int k = 0; k < 49; k++) {
        float v = warp_sum(inter[k]);
        if (lane == 0) wsum[wid][k] = v;
    }
    #pragma unroll
    for (int s = 0; s < 8; s++) {
        float v = warp_sum(sp[s]);
        if (lane == 0) wsum[wid][49 + s] = v;
    }
    #pragma unroll
    for (int s = 0; s < 8; s++) {
        float v = warp_sum(sg[s]);
        if (lane == 0) wsum[wid][57 + s] = v;
    }
    {
        float v = warp_sum(bgi);
        if (lane == 0) wsum[wid][65] = v;
    }
    __syncthreads();
    if (threadIdx.x < NACC) {
        float v = 0.0f;
        #pragma unroll
        for (int w = 0; w < TPB / 32; w++) v += wsum[w][threadIdx.x];
        g_part[b][chunk][threadIdx.x] = v;
    }
    __threadfence();
    __syncthreads();

    // ---- last block of this batch runs the batch finalize ----
    if (threadIdx.x == 0) {
        int old = atomicAdd(&cnt_batch[b], 1);
        flag_sm = (old == NCHUNK - 1) ? 1 : 0;
    }
    __syncthreads();
    if (!flag_sm) return;
    __threadfence();   // acquire: see all chunks' g_part writes

    if (wid == 0) {
        int n = num_objects[b];
        if (n > 7) n = 7;
        if (n < 0) n = 0;

        // sum partials over chunks
        for (int k = lane; k < NACC; k += 32) {
            float v = 0.0f;
            #pragma unroll
            for (int c = 0; c < NCHUNK; c++) v += g_part[b][c][k];
            a_sm[k] = v;
        }
        __syncwarp();

        // dice matrix (pred p, gt g) — all 49 entries
        for (int idx = lane; idx < 49; idx += 32) {
            int p = idx / 7, g = idx % 7;
            dice_sm[idx] = (2.0f * a_sm[idx] + EPSF) /
                           (a_sm[50 + p] + a_sm[58 + g] + EPSF);
        }
        __syncwarp();

        // subset DP over pred-slot sets (exact optimal-assignment sum)
        #pragma unroll
        for (int q = 0; q < 4; q++) {
            int S = lane + 32 * q;
            dp_sm[S] = (S == 0) ? 0.0f : -1e30f;
        }
        __syncwarp();
        for (int k = 1; k <= n; k++) {
            float newv[4];
            #pragma unroll
            for (int q = 0; q < 4; q++) {
                int S = lane + 32 * q;
                float best = -1e30f;
                if (__popc(S) == k) {
                    #pragma unroll
                    for (int j = 0; j < 7; j++) {
                        if (S & (1 << j)) {
                            float cand = dp_sm[S & ~(1 << j)] + dice_sm[j * 7 + (k - 1)];
                            best = fmaxf(best, cand);
                        }
                    }
                }
                newv[q] = best;
            }
            __syncwarp();
            #pragma unroll
            for (int q = 0; q < 4; q++) {
                int S = lane + 32 * q;
                if (__popc(S) == k) dp_sm[S] = newv[q];
            }
            __syncwarp();
        }

        float best = -1e30f;
        #pragma unroll
        for (int q = 0; q < 4; q++) {
            int S = lane + 32 * q;
            if (__popc(S) == n) best = fmaxf(best, dp_sm[S]);
        }
        #pragma unroll
        for (int off = 16; off > 0; off >>= 1)
            best = fmaxf(best, __shfl_down_sync(0xffffffffu, best, off));

        if (lane == 0) {
            g_bg[b] = 1.0f - (2.0f * a_sm[65] + EPSF) /
                             (a_sm[49] + a_sm[57] + EPSF);
            g_fg[b] = (n > 0) ? ((float)n - best) : 0.0f;
            g_n[b]  = n;
            __threadfence();

            // ---- global finalize by the last batch finalizer ----
            int gold = atomicAdd(&cnt_global, 1);
            if (gold == NB - 1) {
                __threadfence();
                float bg = 0.0f, fg = 0.0f;
                int cn = 0;
                #pragma unroll
                for (int bb = 0; bb < NB; bb++) {
                    bg += g_bg[bb];
                    fg += g_fg[bb];
                    cn += g_n[bb];
                }
                float bg_loss = bg / (float)NB;
                float fg_loss = (cn > 0) ? (fg / (float)cn) : 0.0f;
                out[0] = bg_loss + fg_loss;
                // reset counters for the next graph replay
                #pragma unroll
                for (int bb = 0; bb < NB; bb++) cnt_batch[bb] = 0;
                cnt_global = 0;
                __threadfence();
            }
        }
    }
}

extern "C" void kernel_launch(void* const* d_in, const int* in_sizes, int n_in,
                              void* d_out, int out_size) {
    const float* pred = (const float*)d_in[0];
    const float* gt   = (const float*)d_in[1];
    const int*   nobj = (const int*)d_in[2];
    float* out = (float*)d_out;

    fused_kernel<<<NB * NCHUNK, TPB>>>(pred, gt, nobj, out);
}

// round 14
// speedup vs baseline: 1.2339x; 1.0626x over previous
#include <cuda_runtime.h>
#include <stdint.h>

#define EPSF 1e-6f

#define NB 32
#define NS 8
#define HW 65536
#define HW2 (HW / 2)
#define NACC 66
// per-batch accumulator layout:
//   [0..48]  fg inter[p*7+g]  (pred slot p+1, gt slot g+1)
//   [49..56] sum_pred[s], [57..64] sum_gt[s], [65] bg inter

#define NCHUNK 13
#define TPB 128

__device__ float g_part[NB][NCHUNK][NACC];
__device__ float g_bg[NB];
__device__ float g_fg[NB];
__device__ int   g_n[NB];
__device__ int   cnt_batch[NB];   // zero-init; restored by kernel each run
__device__ int   cnt_global;

__device__ __forceinline__ float warp_sum(float v) {
    #pragma unroll
    for (int off = 16; off > 0; off >>= 1)
        v += __shfl_down_sync(0xffffffffu, v, off);
    return v;
}

struct Acc {
    float inter[49];
    float sp[8], sg[8];
    float bgi;
};

__device__ __forceinline__ void load16(const float2* __restrict__ pb,
                                       const float2* __restrict__ gb,
                                       int pix, float2 (&p)[8], float2 (&g)[8]) {
    #pragma unroll
    for (int s = 0; s < 8; s++) p[s] = __ldcs(&pb[s * HW2 + pix]);
    #pragma unroll
    for (int s = 0; s < 8; s++) g[s] = __ldcs(&gb[s * HW2 + pix]);
}

__device__ __forceinline__ void consume(Acc& a, const float2 (&p)[8],
                                        const float2 (&g)[8]) {
    #pragma unroll
    for (int s = 0; s < 8; s++) a.sp[s] += p[s].x + p[s].y;
    #pragma unroll
    for (int s = 0; s < 8; s++) a.sg[s] += g[s].x + g[s].y;
    a.bgi = fmaf(p[0].x, g[0].x, a.bgi);
    a.bgi = fmaf(p[0].y, g[0].y, a.bgi);
    #pragma unroll
    for (int i = 1; i < 8; i++)
        #pragma unroll
        for (int j = 1; j < 8; j++) {
            float acc = a.inter[(i - 1) * 7 + (j - 1)];
            acc = fmaf(p[i].x, g[j].x, acc);
            acc = fmaf(p[i].y, g[j].y, acc);
            a.inter[(i - 1) * 7 + (j - 1)] = acc;
        }
}

__global__ __launch_bounds__(TPB, 3)
void fused_kernel(const float* __restrict__ pred, const float* __restrict__ gt,
                  const int* __restrict__ num_objects, float* __restrict__ out) {
    const int b = blockIdx.x / NCHUNK;
    const int chunk = blockIdx.x % NCHUNK;
    // range-based chunking in float2 units (no divisibility requirement)
    const int lo = (int)(((long long)chunk * HW2) / NCHUNK);
    const int hi = (int)(((long long)(chunk + 1) * HW2) / NCHUNK);

    const float2* __restrict__ pb = (const float2*)(pred + (size_t)b * NS * HW);
    const float2* __restrict__ gb = (const float2*)(gt   + (size_t)b * NS * HW);

    Acc a;
    #pragma unroll
    for (int k = 0; k < 49; k++) a.inter[k] = 0.0f;
    #pragma unroll
    for (int s = 0; s < 8; s++) { a.sp[s] = 0.0f; a.sg[s] = 0.0f; }
    a.bgi = 0.0f;

    // software-pipelined main loop: prefetch next iter's 16 loads before
    // consuming the current iter -> forces all 16 LDGs in flight.
    const int iters = (hi - lo) / TPB;   // uniform across threads in block
    int pix = lo + threadIdx.x;

    float2 cp[8], cg[8];
    if (iters > 0) load16(pb, gb, pix, cp, cg);
    #pragma unroll 2
    for (int it = 1; it < iters; it++) {
        float2 np[8], ng[8];
        load16(pb, gb, pix + TPB, np, ng);
        consume(a, cp, cg);
        #pragma unroll
        for (int s = 0; s < 8; s++) { cp[s] = np[s]; cg[s] = ng[s]; }
        pix += TPB;
    }
    if (iters > 0) { consume(a, cp, cg); pix += TPB; }
    // epilogue: remainder (< TPB pixels)
    if (pix < hi) {
        float2 ep[8], eg[8];
        load16(pb, gb, pix, ep, eg);
        consume(a, ep, eg);
    }

    // ---- block reduction -> g_part[b][chunk][*] ----
    __shared__ float wsum[TPB / 32][NACC];
    __shared__ float a_sm[NACC];
    __shared__ float dice_sm[49];
    __shared__ float dp_sm[128];
    __shared__ int   flag_sm;

    const int wid = threadIdx.x >> 5;
    const int lane = threadIdx.x & 31;

    #pragma unroll
    for (int k = 0; k < 49; k++) {
        float v = warp_sum(a.inter[k]);
        if (lane == 0) wsum[wid][k] = v;
    }
    #pragma unroll
    for (int s = 0; s < 8; s++) {
        float v = warp_sum(a.sp[s]);
        if (lane == 0) wsum[wid][49 + s] = v;
    }
    #pragma unroll
    for (int s = 0; s < 8; s++) {
        float v = warp_sum(a.sg[s]);
        if (lane == 0) wsum[wid][57 + s] = v;
    }
    {
        float v = warp_sum(a.bgi);
        if (lane == 0) wsum[wid][65] = v;
    }
    __syncthreads();
    if (threadIdx.x < NACC) {
        float v = 0.0f;
        #pragma unroll
        for (int w = 0; w < TPB / 32; w++) v += wsum[w][threadIdx.x];
        g_part[b][chunk][threadIdx.x] = v;
    }
    __threadfence();
    __syncthreads();

    // ---- last block of this batch runs the batch finalize ----
    if (threadIdx.x == 0) {
        int old = atomicAdd(&cnt_batch[b], 1);
        flag_sm = (old == NCHUNK - 1) ? 1 : 0;
    }
    __syncthreads();
    if (!flag_sm) return;
    __threadfence();   // acquire: see all chunks' g_part writes

    if (wid == 0) {
        int n = num_objects[b];
        if (n > 7) n = 7;
        if (n < 0) n = 0;

        // sum partials over chunks
        for (int k = lane; k < NACC; k += 32) {
            float v = 0.0f;
            #pragma unroll
            for (int c = 0; c < NCHUNK; c++) v += g_part[b][c][k];
            a_sm[k] = v;
        }
        __syncwarp();

        // dice matrix (pred p, gt g) — all 49 entries
        for (int idx = lane; idx < 49; idx += 32) {
            int p = idx / 7, g = idx % 7;
            dice_sm[idx] = (2.0f * a_sm[idx] + EPSF) /
                           (a_sm[50 + p] + a_sm[58 + g] + EPSF);
        }
        __syncwarp();

        // subset DP over pred-slot sets (exact optimal-assignment sum)
        #pragma unroll
        for (int q = 0; q < 4; q++) {
            int S = lane + 32 * q;
            dp_sm[S] = (S == 0) ? 0.0f : -1e30f;
        }
        __syncwarp();
        for (int k = 1; k <= n; k++) {
            float newv[4];
            #pragma unroll
            for (int q = 0; q < 4; q++) {
                int S = lane + 32 * q;
                float best = -1e30f;
                if (__popc(S) == k) {
                    #pragma unroll
                    for (int j = 0; j < 7; j++) {
                        if (S & (1 << j)) {
                            float cand = dp_sm[S & ~(1 << j)] + dice_sm[j * 7 + (k - 1)];
                            best = fmaxf(best, cand);
                        }
                    }
                }
                newv[q] = best;
            }
            __syncwarp();
            #pragma unroll
            for (int q = 0; q < 4; q++) {
                int S = lane + 32 * q;
                if (__popc(S) == k) dp_sm[S] = newv[q];
            }
            __syncwarp();
        }

        float best = -1e30f;
        #pragma unroll
        for (int q = 0; q < 4; q++) {
            int S = lane + 32 * q;
            if (__popc(S) == n) best = fmaxf(best, dp_sm[S]);
        }
        #pragma unroll
        for (int off = 16; off > 0; off >>= 1)
            best = fmaxf(best, __shfl_down_sync(0xffffffffu, best, off));

        if (lane == 0) {
            g_bg[b] = 1.0f - (2.0f * a_sm[65] + EPSF) /
                             (a_sm[49] + a_sm[57] + EPSF);
            g_fg[b] = (n > 0) ? ((float)n - best) : 0.0f;
            g_n[b]  = n;
            __threadfence();

            // ---- global finalize by the last batch finalizer ----
            int gold = atomicAdd(&cnt_global, 1);
            if (gold == NB - 1) {
                __threadfence();
                float bg = 0.0f, fg = 0.0f;
                int cn = 0;
                #pragma unroll
                for (int bb = 0; bb < NB; bb++) {
                    bg += g_bg[bb];
                    fg += g_fg[bb];
                    cn += g_n[bb];
                }
                float bg_loss = bg / (float)NB;
                float fg_loss = (cn > 0) ? (fg / (float)cn) : 0.0f;
                out[0] = bg_loss + fg_loss;
                // reset counters for the next graph replay
                #pragma unroll
                for (int bb = 0; bb < NB; bb++) cnt_batch[bb] = 0;
                cnt_global = 0;
                __threadfence();
            }
        }
    }
}

extern "C" void kernel_launch(void* const* d_in, const int* in_sizes, int n_in,
                              void* d_out, int out_size) {
    const float* pred = (const float*)d_in[0];
    const float* gt   = (const float*)d_in[1];
    const int*   nobj = (const int*)d_in[2];
    float* out = (float*)d_out;

    fused_kernel<<<NB * NCHUNK, TPB>>>(pred, gt, nobj, out);
}